// round 9
// baseline (speedup 1.0000x reference)
#include <cuda_runtime.h>

// MaxUnpool2D: B=8, H=W=128, C=64, KH=KW=2, HOUT=WOUT=256.
// Mask guarantees each input element's target lies inside its own disjoint 2x2
// output window => unique targets (plain stores), windows tile the output
// exactly (no zero-fill pass).
//
// Round 8 (re-bench; R7/R8 were broker infra failures — R0 failed identically
// on the empty stub): cross-replay L2 residency. 256-bit evict_last loads
// (.v8.b32, the only form ptxas accepts on sm_103) pin the replay-invariant
// inputs (67 MB < 126 MB L2); the 134 MB output stream is stored evict-first
// (__stcs) so it drains without displacing the pinned inputs. Target:
// steady-state DRAM traffic 201 -> ~140 MB per graph replay.

#define B_    8
#define H_    128
#define W_    128
#define C_    64
#define HOUT_ 256
#define WOUT_ 256
#define C4_   16                      // float4 groups per pixel
#define C8_   8                       // 8-channel groups per pixel
#define NT_   (B_ * H_ * W_ * C8_)    // 1,048,576 threads

__device__ __forceinline__ void ld_evict_last_8x32(const void* p, unsigned r[8]) {
    asm volatile(
        "ld.global.L2::evict_last.v8.b32 {%0,%1,%2,%3,%4,%5,%6,%7}, [%8];"
        : "=r"(r[0]), "=r"(r[1]), "=r"(r[2]), "=r"(r[3]),
          "=r"(r[4]), "=r"(r[5]), "=r"(r[6]), "=r"(r[7])
        : "l"(p));
}

__global__ void __launch_bounds__(256)
max_unpool_kernel(const float* __restrict__ x,
                  const int*   __restrict__ mk,
                  float4*      __restrict__ out4)
{
    const int t = blockIdx.x * 256 + threadIdx.x;

    // Pin the (replay-invariant) inputs in L2. 32-byte aligned: t*8 elems.
    unsigned vr[8], mr[8];
    ld_evict_last_8x32(x + (size_t)t * 8, vr);
    ld_evict_last_8x32(mk + (size_t)t * 8, mr);

    // t layout: (((b*H + h)*W + w) * C8 + c8)
    const int c8 = t & (C8_ - 1);
    const int w  = (t >> 3) & (W_ - 1);
    const int h  = (t >> 10) & (H_ - 1);
    const int b  = t >> 17;

    // Flat per-batch element index of channel c8*8 at window pos (0,0).
    const int p00   = (h * 2 * WOUT_ + w * 2) * C_ + c8 * 8;
    const int base4 = b * (HOUT_ * WOUT_ * C4_) + (p00 >> 2);

#pragma unroll
    for (int dh = 0; dh < 2; ++dh) {
#pragma unroll
        for (int dw = 0; dw < 2; ++dw) {
            const int p = p00 + dh * (WOUT_ * C_) + dw * C_;
            float4 o0, o1;
            o0.x = ((int)mr[0] == p + 0) ? __uint_as_float(vr[0]) : 0.0f;
            o0.y = ((int)mr[1] == p + 1) ? __uint_as_float(vr[1]) : 0.0f;
            o0.z = ((int)mr[2] == p + 2) ? __uint_as_float(vr[2]) : 0.0f;
            o0.w = ((int)mr[3] == p + 3) ? __uint_as_float(vr[3]) : 0.0f;
            o1.x = ((int)mr[4] == p + 4) ? __uint_as_float(vr[4]) : 0.0f;
            o1.y = ((int)mr[5] == p + 5) ? __uint_as_float(vr[5]) : 0.0f;
            o1.z = ((int)mr[6] == p + 6) ? __uint_as_float(vr[6]) : 0.0f;
            o1.w = ((int)mr[7] == p + 7) ? __uint_as_float(vr[7]) : 0.0f;
            float4* dst = out4 + base4 + dh * (WOUT_ * C4_) + dw * C4_;
            __stcs(dst, o0);
            __stcs(dst + 1, o1);
        }
    }
}

extern "C" void kernel_launch(void* const* d_in, const int* in_sizes, int n_in,
                              void* d_out, int out_size)
{
    const float* x  = (const float*)d_in[0];  // input_pool f32 [8,128,128,64]
    const int*   mk = (const int*)d_in[1];    // pool_mask  i32 [8,128,128,64]
    float4* out4 = (float4*)d_out;            // [8,256,256,64] f32

    const int block = 256;
    const int grid  = NT_ / block;            // 4096 blocks
    max_unpool_kernel<<<grid, block>>>(x, mk, out4);
}

// round 11
// speedup vs baseline: 1.1750x; 1.1750x over previous
#include <cuda_runtime.h>

// MaxUnpool2D: B=8, H=W=128, C=64, KH=KW=2, HOUT=WOUT=256.
// Mask guarantees each input element's target lies inside its own disjoint 2x2
// output window => unique targets (plain stores), windows tile the output
// exactly (no zero-fill pass).
//
// Round 10: revert to R1's plain float4 memory ops (hints regressed or were
// neutral), fix the real cold-path limiter: short-CTA churn / low per-warp
// MLP. 2048 CTAs, 4 elements per thread (stride = total threads, coalesced),
// software prefetch of the next element's loads before the current element's
// stores so the read stream never idles behind the store burst.

#define B_    8
#define H_    128
#define W_    128
#define C_    64
#define HOUT_ 256
#define WOUT_ 256
#define C4_   16                          // float4 groups per pixel
#define N4_   (B_ * H_ * W_ * C4_)        // 2,097,152 float4 elements
#define GRID_ 2048
#define BLK_  256
#define STRIDE_ (GRID_ * BLK_)            // 524,288
#define ITER_  (N4_ / STRIDE_)            // 4

__device__ __forceinline__ void unpool_one(int t, float4 v, int4 m,
                                           float4* __restrict__ out4)
{
    // t layout: (((b*H + h)*W + w) * C4 + c4)
    const int c4 = t & (C4_ - 1);
    const int w  = (t >> 4) & (W_ - 1);
    const int h  = (t >> 11) & (H_ - 1);
    const int b  = t >> 18;

    // Flat per-batch element index of channel c4*4 at window pos (0,0).
    const int p00   = (h * 2 * WOUT_ + w * 2) * C_ + c4 * 4;
    const int base4 = b * (HOUT_ * WOUT_ * C4_) + (p00 >> 2);

    const float vx[4] = {v.x, v.y, v.z, v.w};
    const int   mi[4] = {m.x, m.y, m.z, m.w};

#pragma unroll
    for (int dh = 0; dh < 2; ++dh) {
#pragma unroll
        for (int dw = 0; dw < 2; ++dw) {
            const int p = p00 + dh * (WOUT_ * C_) + dw * C_;
            float4 o;
            o.x = (mi[0] == p + 0) ? vx[0] : 0.0f;
            o.y = (mi[1] == p + 1) ? vx[1] : 0.0f;
            o.z = (mi[2] == p + 2) ? vx[2] : 0.0f;
            o.w = (mi[3] == p + 3) ? vx[3] : 0.0f;
            out4[base4 + dh * (WOUT_ * C4_) + dw * C4_] = o;
        }
    }
}

__global__ void __launch_bounds__(BLK_)
max_unpool_kernel(const float4* __restrict__ x4,
                  const int4*   __restrict__ m4,
                  float4*       __restrict__ out4)
{
    int t = blockIdx.x * BLK_ + threadIdx.x;

    // Prime the pipeline.
    float4 v = x4[t];
    int4   m = m4[t];

#pragma unroll
    for (int i = 0; i < ITER_; ++i) {
        const int tn = t + STRIDE_;
        float4 vn;
        int4   mn;
        if (i + 1 < ITER_) {
            // Prefetch next element BEFORE this element's stores, so the
            // read stream overlaps the store burst.
            vn = x4[tn];
            mn = m4[tn];
        }
        unpool_one(t, v, m, out4);
        t = tn;
        v = vn;
        m = mn;
    }
}

extern "C" void kernel_launch(void* const* d_in, const int* in_sizes, int n_in,
                              void* d_out, int out_size)
{
    const float4* x4 = (const float4*)d_in[0];  // input_pool f32 [8,128,128,64]
    const int4*   m4 = (const int4*)d_in[1];    // pool_mask  i32 [8,128,128,64]
    float4* out4 = (float4*)d_out;              // [8,256,256,64] f32

    max_unpool_kernel<<<GRID_, BLK_>>>(x4, m4, out4);
}